// round 13
// baseline (speedup 1.0000x reference)
#include <cuda_runtime.h>
#include <cuda_bf16.h>

#define N_NODES 100000
#define KNN 16
#define D 128

// Scratch (static device arrays — no allocation anywhere)
__device__ float g_P[(size_t)N_NODES * D];   // feature @ Wm
__device__ float g_S[(size_t)N_NODES * D];   // feature @ Ws
__device__ int   g_idx_is64;

// ---------------------------------------------------------------------------
// helpers
// ---------------------------------------------------------------------------
__device__ __forceinline__ unsigned f2tf(float x) {
    unsigned r;
    asm("cvt.rna.tf32.f32 %0, %1;" : "=r"(r) : "f"(x));
    return r;
}

__device__ __forceinline__ void mma_tf32(float c[4],
                                         unsigned a0, unsigned a1,
                                         unsigned a2, unsigned a3,
                                         unsigned b0, unsigned b1) {
    asm volatile(
        "mma.sync.aligned.m16n8k8.row.col.f32.tf32.tf32.f32 "
        "{%0,%1,%2,%3}, {%4,%5,%6,%7}, {%8,%9}, {%0,%1,%2,%3};"
        : "+f"(c[0]), "+f"(c[1]), "+f"(c[2]), "+f"(c[3])
        : "r"(a0), "r"(a1), "r"(a2), "r"(a3), "r"(b0), "r"(b1));
}

// ---------------------------------------------------------------------------
// Kernel 1: 3xTF32 tensor-core GEMM  C[N,128] = feature[N,128] @ W_half
//   blockIdx.y = 0 -> Wm -> g_P ; blockIdx.y = 1 -> Ws -> g_S
// W-half stays resident in smem; each block processes CHUNKS=4 row-chunks
// of 64 rows (amortizes the 64KB W load + prologue over 4x the mma work).
// 8 warps as 2(m) x 4(n); warp tile 32x32. 3-term compensation:
//   C = ah*bh + al*bh + ah*bl  (~fp32 accuracy; measured rel_err ~1e-6)
// Smem ~104.5KB -> 2 CTAs/SM.
// Block (0,0) also does idx dtype detection (parallel 4KB read):
// genuine int64 indices are all < N_NODES; int32 viewed as int64 is not.
// ---------------------------------------------------------------------------
#define BROWS 64
#define CHUNKS 4
#define WSTRIDE 136

extern __shared__ float smem_dyn[];

__global__ __launch_bounds__(256, 2) void pgnn_gemm_kernel(
    const float* __restrict__ A,     // feature [N,128]
    const float* __restrict__ W,     // W_hidden [256,128]
    const unsigned long long* __restrict__ idx_u64)
{
    float* Wsm = smem_dyn;                   // [128][136]
    float* Asm = smem_dyn + 128 * WSTRIDE;   // [64][136]

    const int tid  = threadIdx.x;
    const int wid  = tid >> 5;
    const int lane = tid & 31;
    const int q    = lane >> 2;   // groupID 0..7
    const int s    = lane & 3;    // threadID_in_group 0..3

    // ---- dtype detection, folded into block (0,0) ----
    if (blockIdx.x == 0 && blockIdx.y == 0) {
        unsigned long long v0 = idx_u64[tid * 2];
        unsigned long long v1 = idx_u64[tid * 2 + 1];
        int ok = (v0 < (unsigned long long)N_NODES) &&
                 (v1 < (unsigned long long)N_NODES);
        int all_ok = __syncthreads_and(ok);
        if (tid == 0) g_idx_is64 = all_ok ? 1 : 0;
    }

    const float* Whalf = W + (size_t)blockIdx.y * 128 * 128;
    float* dst = blockIdx.y ? g_S : g_P;

    // ---- load W half [128][128] into Wsm once ----
    #pragma unroll
    for (int i = 0; i < 16; i++) {
        int e  = i * 256 + tid;          // float4 index, 0..4095
        int d  = e >> 5;
        int o4 = (e & 31) * 4;
        float4 v = *(const float4*)(Whalf + d * 128 + o4);
        *(float4*)(Wsm + d * WSTRIDE + o4) = v;
    }

    const int warp_m = wid >> 2;  // 0..1
    const int warp_n = wid & 3;   // 0..3
    const int rbase  = warp_m * 32;
    const int cbase  = warp_n * 32;

    for (int ch = 0; ch < CHUNKS; ch++) {
        const long long base = ((long long)blockIdx.x * CHUNKS + ch) * BROWS;
        if (base >= N_NODES) break;
        __syncthreads();   // covers Wsm (iter 0) + Asm reuse (later iters)

        // ---- load A tile [64][128] into Asm ----
        #pragma unroll
        for (int i = 0; i < 8; i++) {
            int e  = i * 256 + tid;      // float4 index, 0..2047
            int r  = e >> 5;
            int c4 = (e & 31) * 4;
            long long grow = base + r;
            float4 v = make_float4(0.f, 0.f, 0.f, 0.f);
            if (grow < N_NODES) v = *(const float4*)(A + grow * D + c4);
            *(float4*)(Asm + r * WSTRIDE + c4) = v;
        }
        __syncthreads();

        float acc[2][4][4];
        #pragma unroll
        for (int t = 0; t < 2; t++)
            #pragma unroll
            for (int j = 0; j < 4; j++)
                #pragma unroll
                for (int i = 0; i < 4; i++) acc[t][j][i] = 0.f;

        #pragma unroll 2
        for (int kc = 0; kc < 16; kc++) {
            const int k0 = kc * 8;

            // ---- A fragments for 2 m-tiles, tf32 hi/lo split ----
            unsigned ah[2][4], al[2][4];
            #pragma unroll
            for (int t = 0; t < 2; t++) {
                int r0 = rbase + t * 16 + q;
                float a0 = Asm[(r0)     * WSTRIDE + k0 + s];
                float a1 = Asm[(r0 + 8) * WSTRIDE + k0 + s];
                float a2 = Asm[(r0)     * WSTRIDE + k0 + 4 + s];
                float a3 = Asm[(r0 + 8) * WSTRIDE + k0 + 4 + s];
                ah[t][0] = f2tf(a0); al[t][0] = f2tf(a0 - __uint_as_float(ah[t][0]));
                ah[t][1] = f2tf(a1); al[t][1] = f2tf(a1 - __uint_as_float(ah[t][1]));
                ah[t][2] = f2tf(a2); al[t][2] = f2tf(a2 - __uint_as_float(ah[t][2]));
                ah[t][3] = f2tf(a3); al[t][3] = f2tf(a3 - __uint_as_float(ah[t][3]));
            }

            // ---- 4 n-tiles: B fragments + 3-term mma ----
            #pragma unroll
            for (int j = 0; j < 4; j++) {
                int col = cbase + j * 8 + q;
                float b0 = Wsm[(k0 + s)     * WSTRIDE + col];
                float b1 = Wsm[(k0 + 4 + s) * WSTRIDE + col];
                unsigned bh0 = f2tf(b0), bh1 = f2tf(b1);
                unsigned bl0 = f2tf(b0 - __uint_as_float(bh0));
                unsigned bl1 = f2tf(b1 - __uint_as_float(bh1));
                #pragma unroll
                for (int t = 0; t < 2; t++) {
                    mma_tf32(acc[t][j], ah[t][0], ah[t][1], ah[t][2], ah[t][3], bh0, bh1);
                    mma_tf32(acc[t][j], al[t][0], al[t][1], al[t][2], al[t][3], bh0, bh1);
                    mma_tf32(acc[t][j], ah[t][0], ah[t][1], ah[t][2], ah[t][3], bl0, bl1);
                }
            }
        }

        // ---- epilogue: float2 stores ----
        #pragma unroll
        for (int t = 0; t < 2; t++) {
            long long row0 = base + rbase + t * 16 + q;
            long long row8 = row0 + 8;
            #pragma unroll
            for (int j = 0; j < 4; j++) {
                int col = cbase + j * 8 + s * 2;
                if (row0 < N_NODES)
                    *(float2*)(dst + row0 * D + col) =
                        make_float2(acc[t][j][0], acc[t][j][1]);
                if (row8 < N_NODES)
                    *(float2*)(dst + row8 * D + col) =
                        make_float2(acc[t][j][2], acc[t][j][3]);
            }
        }
    }
}

// ---------------------------------------------------------------------------
// Kernel 2: gather + relu + reductions. Warp-per-node, lane owns 4 channels.
// pos[n,k] reduction: per-lane partials in registers (FMA pipe), then ONE
// smem transpose per node: 4 aligned STS.128 + 32 conflict-free LDS
// (read phase: fixed l per iter -> lanes 0..15 hit consecutive floats).
// Row stride 16 floats = 64B keeps float4 stores aligned (no padding!).
// ---------------------------------------------------------------------------
__global__ __launch_bounds__(256) void pgnn_gather_kernel(
    const float* __restrict__ dm,        // dists_max [N,16]
    const void*  __restrict__ idxbuf,    // dists_argmax [N,16] (i32 or i64)
    const float* __restrict__ bh,        // b_hidden [128]
    const float* __restrict__ wo,        // w_out [128]
    const float* __restrict__ bo,        // b_out [1]
    float* __restrict__ out)             // [N*16 | N*128]
{
    __shared__ float s_tr[8][32][16];    // [warp][lane][k], 64B lane stride

    const int warp = threadIdx.x >> 5;
    const int lane = threadIdx.x & 31;
    const int n = blockIdx.x * 8 + warp;
    if (n >= N_NODES) return;

    const int c4 = lane * 4;

    int   my_idx = 0;
    float my_dm  = 0.f;
    if (lane < KNN) {
        long long v;
        if (g_idx_is64) v = ((const long long*)idxbuf)[(long long)n * KNN + lane];
        else            v = (long long)((const int*)idxbuf)[(long long)n * KNN + lane];
        if (v < 0) v = 0;
        if (v >= N_NODES) v = N_NODES - 1;
        my_idx = (int)v;
        my_dm  = dm[(long long)n * KNN + lane];
    }

    float4 s4 = *(const float4*)(g_S + (long long)n * D + c4);
    float4 b4 = __ldg((const float4*)(bh + c4));
    float4 w4 = __ldg((const float4*)(wo + c4));
    float  bout = __ldg(bo);
    float4 cst = make_float4(s4.x + b4.x, s4.y + b4.y, s4.z + b4.z, s4.w + b4.w);

    float4 acc = make_float4(0.f, 0.f, 0.f, 0.f);
    float  pos_part[KNN];

    #pragma unroll
    for (int h = 0; h < 2; h++) {
        // batch of 8 gathers (overlap latency with compute below)
        float4 p[8];
        #pragma unroll
        for (int k = 0; k < 8; k++) {
            int j = __shfl_sync(0xFFFFFFFFu, my_idx, h * 8 + k);
            p[k] = __ldg((const float4*)(g_P + (long long)j * D + c4));
        }
        #pragma unroll
        for (int k = 0; k < 8; k++) {
            int   kk = h * 8 + k;
            float dk = __shfl_sync(0xFFFFFFFFu, my_dm, kk);

            float hx = fmaxf(fmaf(dk, p[k].x, cst.x), 0.f);
            float hy = fmaxf(fmaf(dk, p[k].y, cst.y), 0.f);
            float hz = fmaxf(fmaf(dk, p[k].z, cst.z), 0.f);
            float hw = fmaxf(fmaf(dk, p[k].w, cst.w), 0.f);

            acc.x += hx; acc.y += hy; acc.z += hz; acc.w += hw;
            pos_part[kk] = fmaf(hx, w4.x, fmaf(hy, w4.y, fmaf(hz, w4.z, hw * w4.w)));
        }
    }

    // ---- transpose-reduce pos_part across lanes (one smem pass) ----
    #pragma unroll
    for (int i = 0; i < 4; i++)
        *(float4*)&s_tr[warp][lane][i * 4] =
            make_float4(pos_part[i * 4], pos_part[i * 4 + 1],
                        pos_part[i * 4 + 2], pos_part[i * 4 + 3]);
    __syncwarp();

    if (lane < KNN) {
        float sum = bout;
        #pragma unroll
        for (int l = 0; l < 32; l++) sum += s_tr[warp][l][lane];
        out[(long long)n * KNN + lane] = sum;
    }

    // out_structure: one STG.128 per lane
    const float inv = 1.f / (float)KNN;
    float4 os = make_float4(acc.x * inv, acc.y * inv, acc.z * inv, acc.w * inv);
    *(float4*)(out + (long long)N_NODES * KNN + (long long)n * D + c4) = os;
}

// ---------------------------------------------------------------------------
extern "C" void kernel_launch(void* const* d_in, const int* in_sizes, int n_in,
                              void* d_out, int out_size)
{
    const float* feature = (const float*)d_in[0];   // [N,128]
    const float* dmax    = (const float*)d_in[1];   // [N,16]
    const void*  dargm   = (const void*)d_in[2];    // [N,16] i32/i64
    const float* W       = (const float*)d_in[3];   // [256,128]
    const float* bh      = (const float*)d_in[4];   // [128]
    const float* wo      = (const float*)d_in[5];   // [128,1]
    const float* bo      = (const float*)d_in[6];   // [1]
    float* out = (float*)d_out;

    size_t smem_bytes = (size_t)(128 * WSTRIDE + BROWS * WSTRIDE) * sizeof(float); // ~104.5 KB
    cudaFuncSetAttribute(pgnn_gemm_kernel,
                         cudaFuncAttributeMaxDynamicSharedMemorySize,
                         (int)smem_bytes);
    dim3 grid((N_NODES + BROWS * CHUNKS - 1) / (BROWS * CHUNKS), 2);   // 391 x 2
    pgnn_gemm_kernel<<<grid, 256, smem_bytes>>>(feature, W,
                                                (const unsigned long long*)dargm);

    pgnn_gather_kernel<<<(N_NODES + 7) / 8, 256>>>(dmax, dargm, bh, wo, bo, out);
}

// round 16
// speedup vs baseline: 1.1530x; 1.1530x over previous
#include <cuda_runtime.h>
#include <cuda_bf16.h>

#define N_NODES 100000
#define KNN 16
#define D 128

// Scratch (static device arrays — no allocation anywhere)
__device__ float g_P[(size_t)N_NODES * D];   // feature @ Wm
__device__ float g_S[(size_t)N_NODES * D];   // feature @ Ws
__device__ int   g_idx_is64;

// ---------------------------------------------------------------------------
// helpers
// ---------------------------------------------------------------------------
__device__ __forceinline__ unsigned f2tf(float x) {
    unsigned r;
    asm("cvt.rna.tf32.f32 %0, %1;" : "=r"(r) : "f"(x));
    return r;
}

__device__ __forceinline__ void mma_tf32(float c[4],
                                         unsigned a0, unsigned a1,
                                         unsigned a2, unsigned a3,
                                         unsigned b0, unsigned b1) {
    asm volatile(
        "mma.sync.aligned.m16n8k8.row.col.f32.tf32.tf32.f32 "
        "{%0,%1,%2,%3}, {%4,%5,%6,%7}, {%8,%9}, {%0,%1,%2,%3};"
        : "+f"(c[0]), "+f"(c[1]), "+f"(c[2]), "+f"(c[3])
        : "r"(a0), "r"(a1), "r"(a2), "r"(a3), "r"(b0), "r"(b1));
}

// ---------------------------------------------------------------------------
// Kernel 1: 3xTF32 tensor-core GEMM  C[N,128] = feature[N,128] @ W_half
// (identical to the 239.9us R10 version: one 64-row tile per block,
//  grid 1563 x 2 — the W-resident chunking variant REGRESSED, reverted)
// ---------------------------------------------------------------------------
#define BROWS 64
#define WSTRIDE 136

extern __shared__ float smem_dyn[];

__global__ __launch_bounds__(256, 2) void pgnn_gemm_kernel(
    const float* __restrict__ A,     // feature [N,128]
    const float* __restrict__ W,     // W_hidden [256,128]
    const unsigned long long* __restrict__ idx_u64)
{
    float* Wsm = smem_dyn;                   // [128][136]
    float* Asm = smem_dyn + 128 * WSTRIDE;   // [64][136]

    const int tid  = threadIdx.x;
    const int wid  = tid >> 5;
    const int lane = tid & 31;
    const int q    = lane >> 2;   // groupID 0..7
    const int s    = lane & 3;    // threadID_in_group 0..3

    // ---- dtype detection, folded into block (0,0) ----
    if (blockIdx.x == 0 && blockIdx.y == 0) {
        unsigned long long v0 = idx_u64[tid * 2];
        unsigned long long v1 = idx_u64[tid * 2 + 1];
        int ok = (v0 < (unsigned long long)N_NODES) &&
                 (v1 < (unsigned long long)N_NODES);
        int all_ok = __syncthreads_and(ok);
        if (tid == 0) g_idx_is64 = all_ok ? 1 : 0;
    }

    const float* Whalf = W + (size_t)blockIdx.y * 128 * 128;
    float* dst = blockIdx.y ? g_S : g_P;
    const long long base = (long long)blockIdx.x * BROWS;

    // ---- load W half [128][128] into Wsm ----
    #pragma unroll
    for (int i = 0; i < 16; i++) {
        int e  = i * 256 + tid;          // float4 index, 0..4095
        int d  = e >> 5;
        int o4 = (e & 31) * 4;
        float4 v = *(const float4*)(Whalf + d * 128 + o4);
        *(float4*)(Wsm + d * WSTRIDE + o4) = v;
    }

    // ---- load A tile [64][128] into Asm ----
    #pragma unroll
    for (int i = 0; i < 8; i++) {
        int e  = i * 256 + tid;          // float4 index, 0..2047
        int r  = e >> 5;
        int c4 = (e & 31) * 4;
        long long grow = base + r;
        float4 v = make_float4(0.f, 0.f, 0.f, 0.f);
        if (grow < N_NODES) v = *(const float4*)(A + grow * D + c4);
        *(float4*)(Asm + r * WSTRIDE + c4) = v;
    }
    __syncthreads();

    const int warp_m = wid >> 2;  // 0..1
    const int warp_n = wid & 3;   // 0..3
    const int rbase  = warp_m * 32;
    const int cbase  = warp_n * 32;

    float acc[2][4][4];
    #pragma unroll
    for (int t = 0; t < 2; t++)
        #pragma unroll
        for (int j = 0; j < 4; j++)
            #pragma unroll
            for (int i = 0; i < 4; i++) acc[t][j][i] = 0.f;

    #pragma unroll 2
    for (int kc = 0; kc < 16; kc++) {
        const int k0 = kc * 8;

        // ---- A fragments for 2 m-tiles, with tf32 hi/lo split ----
        unsigned ah[2][4], al[2][4];
        #pragma unroll
        for (int t = 0; t < 2; t++) {
            int r0 = rbase + t * 16 + q;
            float a0 = Asm[(r0)     * WSTRIDE + k0 + s];
            float a1 = Asm[(r0 + 8) * WSTRIDE + k0 + s];
            float a2 = Asm[(r0)     * WSTRIDE + k0 + 4 + s];
            float a3 = Asm[(r0 + 8) * WSTRIDE + k0 + 4 + s];
            ah[t][0] = f2tf(a0); al[t][0] = f2tf(a0 - __uint_as_float(ah[t][0]));
            ah[t][1] = f2tf(a1); al[t][1] = f2tf(a1 - __uint_as_float(ah[t][1]));
            ah[t][2] = f2tf(a2); al[t][2] = f2tf(a2 - __uint_as_float(ah[t][2]));
            ah[t][3] = f2tf(a3); al[t][3] = f2tf(a3 - __uint_as_float(ah[t][3]));
        }

        // ---- 4 n-tiles: B fragments + 3-term mma ----
        #pragma unroll
        for (int j = 0; j < 4; j++) {
            int col = cbase + j * 8 + q;
            float b0 = Wsm[(k0 + s)     * WSTRIDE + col];
            float b1 = Wsm[(k0 + 4 + s) * WSTRIDE + col];
            unsigned bh0 = f2tf(b0), bh1 = f2tf(b1);
            unsigned bl0 = f2tf(b0 - __uint_as_float(bh0));
            unsigned bl1 = f2tf(b1 - __uint_as_float(bh1));
            #pragma unroll
            for (int t = 0; t < 2; t++) {
                mma_tf32(acc[t][j], ah[t][0], ah[t][1], ah[t][2], ah[t][3], bh0, bh1);
                mma_tf32(acc[t][j], al[t][0], al[t][1], al[t][2], al[t][3], bh0, bh1);
                mma_tf32(acc[t][j], ah[t][0], ah[t][1], ah[t][2], ah[t][3], bl0, bl1);
            }
        }
    }

    // ---- epilogue: float2 stores ----
    #pragma unroll
    for (int t = 0; t < 2; t++) {
        long long row0 = base + rbase + t * 16 + q;
        long long row8 = row0 + 8;
        #pragma unroll
        for (int j = 0; j < 4; j++) {
            int col = cbase + j * 8 + s * 2;
            if (row0 < N_NODES)
                *(float2*)(dst + row0 * D + col) =
                    make_float2(acc[t][j][0], acc[t][j][1]);
            if (row8 < N_NODES)
                *(float2*)(dst + row8 * D + col) =
                    make_float2(acc[t][j][2], acc[t][j][3]);
        }
    }
}

// ---------------------------------------------------------------------------
// Kernel 2: gather + relu + reductions. Warp-per-node, lane owns 4 channels.
// pos[n,k] reduction via multi-value SPLIT butterfly: 31 shfls total
// (16 @d=16, then 8/4/2/1 halving the per-lane value count) instead of
// 16 independent 5-stage butterflies (80 shfls). Final: lane l holds the
// complete sum for k = l & 15. No smem, no syncs, occupancy unchanged.
// ---------------------------------------------------------------------------
__global__ __launch_bounds__(256) void pgnn_gather_kernel(
    const float* __restrict__ dm,        // dists_max [N,16]
    const void*  __restrict__ idxbuf,    // dists_argmax [N,16] (i32 or i64)
    const float* __restrict__ bh,        // b_hidden [128]
    const float* __restrict__ wo,        // w_out [128]
    const float* __restrict__ bo,        // b_out [1]
    float* __restrict__ out)             // [N*16 | N*128]
{
    const int warp = threadIdx.x >> 5;
    const int lane = threadIdx.x & 31;
    const int n = blockIdx.x * 8 + warp;
    if (n >= N_NODES) return;

    const int c4 = lane * 4;

    int   my_idx = 0;
    float my_dm  = 0.f;
    if (lane < KNN) {
        long long v;
        if (g_idx_is64) v = ((const long long*)idxbuf)[(long long)n * KNN + lane];
        else            v = (long long)((const int*)idxbuf)[(long long)n * KNN + lane];
        if (v < 0) v = 0;
        if (v >= N_NODES) v = N_NODES - 1;
        my_idx = (int)v;
        my_dm  = dm[(long long)n * KNN + lane];
    }

    float4 s4 = *(const float4*)(g_S + (long long)n * D + c4);
    float4 b4 = __ldg((const float4*)(bh + c4));
    float4 w4 = __ldg((const float4*)(wo + c4));
    float  bout = __ldg(bo);
    float4 cst = make_float4(s4.x + b4.x, s4.y + b4.y, s4.z + b4.z, s4.w + b4.w);

    float4 acc = make_float4(0.f, 0.f, 0.f, 0.f);
    float  v[KNN];   // per-lane partial of pos[n,k], k = index

    #pragma unroll
    for (int h = 0; h < 2; h++) {
        // batch of 8 gathers (overlap latency with compute below)
        float4 p[8];
        #pragma unroll
        for (int k = 0; k < 8; k++) {
            int j = __shfl_sync(0xFFFFFFFFu, my_idx, h * 8 + k);
            p[k] = __ldg((const float4*)(g_P + (long long)j * D + c4));
        }
        #pragma unroll
        for (int k = 0; k < 8; k++) {
            int   kk = h * 8 + k;
            float dk = __shfl_sync(0xFFFFFFFFu, my_dm, kk);

            float hx = fmaxf(fmaf(dk, p[k].x, cst.x), 0.f);
            float hy = fmaxf(fmaf(dk, p[k].y, cst.y), 0.f);
            float hz = fmaxf(fmaf(dk, p[k].z, cst.z), 0.f);
            float hw = fmaxf(fmaf(dk, p[k].w, cst.w), 0.f);

            acc.x += hx; acc.y += hy; acc.z += hz; acc.w += hw;
            v[kk] = fmaf(hx, w4.x, fmaf(hy, w4.y, fmaf(hz, w4.z, hw * w4.w)));
        }
    }

    // ---- multi-value split butterfly: 31 shfls ----
    // stage d=16: full exchange
    #pragma unroll
    for (int k = 0; k < 16; k++)
        v[k] += __shfl_xor_sync(0xFFFFFFFFu, v[k], 16);

    // stage d=8: bit-clear lanes keep k[0..8), bit-set keep k[8..16)
    float w8[8];
    {
        const bool up = (lane & 8) != 0;
        #pragma unroll
        for (int i = 0; i < 8; i++) {
            float send = up ? v[i] : v[i + 8];
            float recv = __shfl_xor_sync(0xFFFFFFFFu, send, 8);
            w8[i] = (up ? v[i + 8] : v[i]) + recv;
        }
    }
    // stage d=4
    float w4r[4];
    {
        const bool up = (lane & 4) != 0;
        #pragma unroll
        for (int i = 0; i < 4; i++) {
            float send = up ? w8[i] : w8[i + 4];
            float recv = __shfl_xor_sync(0xFFFFFFFFu, send, 4);
            w4r[i] = (up ? w8[i + 4] : w8[i]) + recv;
        }
    }
    // stage d=2
    float w2[2];
    {
        const bool up = (lane & 2) != 0;
        #pragma unroll
        for (int i = 0; i < 2; i++) {
            float snd = up ? w4r[i] : w4r[i + 2];
            float rcv = __shfl_xor_sync(0xFFFFFFFFu, snd, 2);
            w2[i] = (up ? w4r[i + 2] : w4r[i]) + rcv;
        }
    }
    // stage d=1
    float w1;
    {
        const bool up = (lane & 1) != 0;
        float snd = up ? w2[0] : w2[1];
        float rcv = __shfl_xor_sync(0xFFFFFFFFu, snd, 1);
        w1 = (up ? w2[1] : w2[0]) + rcv;
    }
    // lane l (l<16) holds the complete sum for k = l
    if (lane < KNN)
        out[(long long)n * KNN + lane] = w1 + bout;

    // out_structure: one STG.128 per lane
    const float inv = 1.f / (float)KNN;
    float4 os = make_float4(acc.x * inv, acc.y * inv, acc.z * inv, acc.w * inv);
    *(float4*)(out + (long long)N_NODES * KNN + (long long)n * D + c4) = os;
}

// ---------------------------------------------------------------------------
extern "C" void kernel_launch(void* const* d_in, const int* in_sizes, int n_in,
                              void* d_out, int out_size)
{
    const float* feature = (const float*)d_in[0];   // [N,128]
    const float* dmax    = (const float*)d_in[1];   // [N,16]
    const void*  dargm   = (const void*)d_in[2];    // [N,16] i32/i64
    const float* W       = (const float*)d_in[3];   // [256,128]
    const float* bh      = (const float*)d_in[4];   // [128]
    const float* wo      = (const float*)d_in[5];   // [128,1]
    const float* bo      = (const float*)d_in[6];   // [1]
    float* out = (float*)d_out;

    size_t smem_bytes = (size_t)(128 * WSTRIDE + BROWS * WSTRIDE) * sizeof(float); // ~104.5 KB
    cudaFuncSetAttribute(pgnn_gemm_kernel,
                         cudaFuncAttributeMaxDynamicSharedMemorySize,
                         (int)smem_bytes);
    dim3 grid((N_NODES + BROWS - 1) / BROWS, 2);   // 1563 x 2
    pgnn_gemm_kernel<<<grid, 256, smem_bytes>>>(feature, W,
                                                (const unsigned long long*)dargm);

    pgnn_gather_kernel<<<(N_NODES + 7) / 8, 256>>>(dmax, dargm, bh, wo, bo, out);
}

// round 17
// speedup vs baseline: 1.4916x; 1.2936x over previous
#include <cuda_runtime.h>
#include <cuda_bf16.h>

#define N_NODES 100000
#define KNN 16
#define D 128

// Scratch (static device arrays — no allocation anywhere)
__device__ float g_P[(size_t)N_NODES * D];   // feature @ Wm
__device__ float g_S[(size_t)N_NODES * D];   // feature @ Ws
__device__ int   g_idx_is64;

// ---------------------------------------------------------------------------
// helpers
// ---------------------------------------------------------------------------
// Split two fp32 (lo_v = even-k element, hi_v = odd-k element) into packed
// bf16x2 head (h) and packed bf16x2 residual (l).
__device__ __forceinline__ uint2 split2_bf16(float lo_v, float hi_v) {
    unsigned h;
    asm("cvt.rn.bf16x2.f32 %0, %1, %2;" : "=r"(h) : "f"(hi_v), "f"(lo_v));
    float lo_h = __uint_as_float(h << 16);
    float hi_h = __uint_as_float(h & 0xffff0000u);
    float lo_r = lo_v - lo_h;
    float hi_r = hi_v - hi_h;
    unsigned l;
    asm("cvt.rn.bf16x2.f32 %0, %1, %2;" : "=r"(l) : "f"(hi_r), "f"(lo_r));
    return make_uint2(h, l);
}

__device__ __forceinline__ void mma_bf16(float c[4],
                                         unsigned a0, unsigned a1,
                                         unsigned a2, unsigned a3,
                                         unsigned b0, unsigned b1) {
    asm volatile(
        "mma.sync.aligned.m16n8k16.row.col.f32.bf16.bf16.f32 "
        "{%0,%1,%2,%3}, {%4,%5,%6,%7}, {%8,%9}, {%0,%1,%2,%3};"
        : "+f"(c[0]), "+f"(c[1]), "+f"(c[2]), "+f"(c[3])
        : "r"(a0), "r"(a1), "r"(a2), "r"(a3), "r"(b0), "r"(b1));
}

// ---------------------------------------------------------------------------
// Kernel 1: 3-term bf16 tensor-core GEMM  C[N,128] = feature[N,128] @ W_half
//   blockIdx.y = 0 -> Wm -> g_P ; blockIdx.y = 1 -> Ws -> g_S
// fp32 operands split ONCE in the prologue into packed-bf16 hi/lo planes in
// smem; mainloop is pure LDS.32 + mma.m16n8k16 (K=16/instr, half the mma
// count of the tf32 version). 3 terms: C = ah*bh + ah*bl + al*bh
// (dropped al*bl ~ 2^-16 rel ~ 1.5e-5 — safely inside 1e-3).
// Planes (uint): Whi/Wlo [64][136] (pairs along k, cols n) — B-frag loads
// conflict-free (bank = 8s+q); Ahi/Alo [64][68] (rows m, pairs along k) —
// A-frag loads conflict-free (bank = 4q+s). Smem ~102KB -> 2 CTAs/SM.
// Block (0,0) also does idx dtype detection (parallel 4KB read).
// ---------------------------------------------------------------------------
#define BROWS 64
#define WP 136   // uint stride of Whi/Wlo rows (k-pair rows, 128 cols used)
#define AP 68    // uint stride of Ahi/Alo rows (64 k-pairs used)

extern __shared__ unsigned usmem[];

__global__ __launch_bounds__(256, 2) void pgnn_gemm_kernel(
    const float* __restrict__ A,     // feature [N,128]
    const float* __restrict__ W,     // W_hidden [256,128]
    const unsigned long long* __restrict__ idx_u64)
{
    unsigned* Whi = usmem;                 // [64][136]
    unsigned* Wlo = Whi + 64 * WP;         // [64][136]
    unsigned* Ahi = Wlo + 64 * WP;         // [64][68]
    unsigned* Alo = Ahi + 64 * AP;         // [64][68]

    const int tid  = threadIdx.x;
    const int wid  = tid >> 5;
    const int lane = tid & 31;
    const int q    = lane >> 2;   // groupID 0..7
    const int s    = lane & 3;    // threadID_in_group 0..3

    // ---- dtype detection, folded into block (0,0) ----
    if (blockIdx.x == 0 && blockIdx.y == 0) {
        unsigned long long v0 = idx_u64[tid * 2];
        unsigned long long v1 = idx_u64[tid * 2 + 1];
        int ok = (v0 < (unsigned long long)N_NODES) &&
                 (v1 < (unsigned long long)N_NODES);
        int all_ok = __syncthreads_and(ok);
        if (tid == 0) g_idx_is64 = all_ok ? 1 : 0;
    }

    const float* Whalf = W + (size_t)blockIdx.y * 128 * 128;
    float* dst = blockIdx.y ? g_S : g_P;
    const long long base = (long long)blockIdx.x * BROWS;

    // ---- load + split W half: pair rows (2p, 2p+1), 4 cols per thread-iter
    #pragma unroll
    for (int i = 0; i < 8; i++) {
        int e  = i * 256 + tid;          // 0..2047
        int p  = e >> 5;                 // k-pair row 0..63
        int c4 = (e & 31) * 4;           // col 0..124
        float4 v0 = *(const float4*)(Whalf + (2 * p)     * 128 + c4);
        float4 v1 = *(const float4*)(Whalf + (2 * p + 1) * 128 + c4);
        uint2 sx = split2_bf16(v0.x, v1.x);
        uint2 sy = split2_bf16(v0.y, v1.y);
        uint2 sz = split2_bf16(v0.z, v1.z);
        uint2 sw = split2_bf16(v0.w, v1.w);
        *(uint4*)(Whi + p * WP + c4) = make_uint4(sx.x, sy.x, sz.x, sw.x);
        *(uint4*)(Wlo + p * WP + c4) = make_uint4(sx.y, sy.y, sz.y, sw.y);
    }

    // ---- load + split A tile [64][128]: pairs contiguous along k ----
    #pragma unroll
    for (int i = 0; i < 8; i++) {
        int e  = i * 256 + tid;          // 0..2047
        int r  = e >> 5;                 // row 0..63
        int c4 = (e & 31) * 4;           // k 0..124 (even)
        long long grow = base + r;
        float4 v = make_float4(0.f, 0.f, 0.f, 0.f);
        if (grow < N_NODES) v = *(const float4*)(A + grow * D + c4);
        uint2 s0 = split2_bf16(v.x, v.y);    // k-pair c4/2
        uint2 s1 = split2_bf16(v.z, v.w);    // k-pair c4/2 + 1
        *(uint2*)(Ahi + r * AP + (c4 >> 1)) = make_uint2(s0.x, s1.x);
        *(uint2*)(Alo + r * AP + (c4 >> 1)) = make_uint2(s0.y, s1.y);
    }
    __syncthreads();

    const int warp_m = wid >> 2;  // 0..1
    const int warp_n = wid & 3;   // 0..3
    const int rbase  = warp_m * 32;
    const int cbase  = warp_n * 32;

    float acc[2][4][4];
    #pragma unroll
    for (int t = 0; t < 2; t++)
        #pragma unroll
        for (int j = 0; j < 4; j++)
            #pragma unroll
            for (int i = 0; i < 4; i++) acc[t][j][i] = 0.f;

    #pragma unroll
    for (int kc = 0; kc < 8; kc++) {
        const int k0p = kc * 8;   // k-pair base (k0 = kc*16)

        // ---- A fragments (hi + lo) for 2 m-tiles ----
        unsigned ah[2][4], al[2][4];
        #pragma unroll
        for (int t = 0; t < 2; t++) {
            int r0 = rbase + t * 16 + q;
            ah[t][0] = Ahi[(r0)     * AP + k0p + s];
            ah[t][1] = Ahi[(r0 + 8) * AP + k0p + s];
            ah[t][2] = Ahi[(r0)     * AP + k0p + 4 + s];
            ah[t][3] = Ahi[(r0 + 8) * AP + k0p + 4 + s];
            al[t][0] = Alo[(r0)     * AP + k0p + s];
            al[t][1] = Alo[(r0 + 8) * AP + k0p + s];
            al[t][2] = Alo[(r0)     * AP + k0p + 4 + s];
            al[t][3] = Alo[(r0 + 8) * AP + k0p + 4 + s];
        }

        // ---- 4 n-tiles: B fragments + 3-term mma ----
        #pragma unroll
        for (int j = 0; j < 4; j++) {
            int col = cbase + j * 8 + q;
            unsigned bh0 = Whi[(k0p + s)     * WP + col];
            unsigned bh1 = Whi[(k0p + 4 + s) * WP + col];
            unsigned bl0 = Wlo[(k0p + s)     * WP + col];
            unsigned bl1 = Wlo[(k0p + 4 + s) * WP + col];
            #pragma unroll
            for (int t = 0; t < 2; t++) {
                mma_bf16(acc[t][j], ah[t][0], ah[t][1], ah[t][2], ah[t][3], bh0, bh1);
                mma_bf16(acc[t][j], al[t][0], al[t][1], al[t][2], al[t][3], bh0, bh1);
                mma_bf16(acc[t][j], ah[t][0], ah[t][1], ah[t][2], ah[t][3], bl0, bl1);
            }
        }
    }

    // ---- epilogue: float2 stores (c layout: (q,2s),(q,2s+1),(q+8,2s),(q+8,2s+1)) ----
    #pragma unroll
    for (int t = 0; t < 2; t++) {
        long long row0 = base + rbase + t * 16 + q;
        long long row8 = row0 + 8;
        #pragma unroll
        for (int j = 0; j < 4; j++) {
            int col = cbase + j * 8 + s * 2;
            if (row0 < N_NODES)
                *(float2*)(dst + row0 * D + col) =
                    make_float2(acc[t][j][0], acc[t][j][1]);
            if (row8 < N_NODES)
                *(float2*)(dst + row8 * D + col) =
                    make_float2(acc[t][j][2], acc[t][j][3]);
        }
    }
}

// ---------------------------------------------------------------------------
// Kernel 2: gather + relu + reductions (unchanged from the 225.6us R16
// version: warp-per-node, batched LDG.128 gathers, 31-shfl split butterfly).
// ---------------------------------------------------------------------------
__global__ __launch_bounds__(256) void pgnn_gather_kernel(
    const float* __restrict__ dm,        // dists_max [N,16]
    const void*  __restrict__ idxbuf,    // dists_argmax [N,16] (i32 or i64)
    const float* __restrict__ bh,        // b_hidden [128]
    const float* __restrict__ wo,        // w_out [128]
    const float* __restrict__ bo,        // b_out [1]
    float* __restrict__ out)             // [N*16 | N*128]
{
    const int warp = threadIdx.x >> 5;
    const int lane = threadIdx.x & 31;
    const int n = blockIdx.x * 8 + warp;
    if (n >= N_NODES) return;

    const int c4 = lane * 4;

    int   my_idx = 0;
    float my_dm  = 0.f;
    if (lane < KNN) {
        long long v;
        if (g_idx_is64) v = ((const long long*)idxbuf)[(long long)n * KNN + lane];
        else            v = (long long)((const int*)idxbuf)[(long long)n * KNN + lane];
        if (v < 0) v = 0;
        if (v >= N_NODES) v = N_NODES - 1;
        my_idx = (int)v;
        my_dm  = dm[(long long)n * KNN + lane];
    }

    float4 s4 = *(const float4*)(g_S + (long long)n * D + c4);
    float4 b4 = __ldg((const float4*)(bh + c4));
    float4 w4 = __ldg((const float4*)(wo + c4));
    float  bout = __ldg(bo);
    float4 cst = make_float4(s4.x + b4.x, s4.y + b4.y, s4.z + b4.z, s4.w + b4.w);

    float4 acc = make_float4(0.f, 0.f, 0.f, 0.f);
    float  v[KNN];   // per-lane partial of pos[n,k]

    #pragma unroll
    for (int h = 0; h < 2; h++) {
        float4 p[8];
        #pragma unroll
        for (int k = 0; k < 8; k++) {
            int j = __shfl_sync(0xFFFFFFFFu, my_idx, h * 8 + k);
            p[k] = __ldg((const float4*)(g_P + (long long)j * D + c4));
        }
        #pragma unroll
        for (int k = 0; k < 8; k++) {
            int   kk = h * 8 + k;
            float dk = __shfl_sync(0xFFFFFFFFu, my_dm, kk);

            float hx = fmaxf(fmaf(dk, p[k].x, cst.x), 0.f);
            float hy = fmaxf(fmaf(dk, p[k].y, cst.y), 0.f);
            float hz = fmaxf(fmaf(dk, p[k].z, cst.z), 0.f);
            float hw = fmaxf(fmaf(dk, p[k].w, cst.w), 0.f);

            acc.x += hx; acc.y += hy; acc.z += hz; acc.w += hw;
            v[kk] = fmaf(hx, w4.x, fmaf(hy, w4.y, fmaf(hz, w4.z, hw * w4.w)));
        }
    }

    // ---- multi-value split butterfly: 31 shfls ----
    #pragma unroll
    for (int k = 0; k < 16; k++)
        v[k] += __shfl_xor_sync(0xFFFFFFFFu, v[k], 16);

    float w8[8];
    {
        const bool up = (lane & 8) != 0;
        #pragma unroll
        for (int i = 0; i < 8; i++) {
            float send = up ? v[i] : v[i + 8];
            float recv = __shfl_xor_sync(0xFFFFFFFFu, send, 8);
            w8[i] = (up ? v[i + 8] : v[i]) + recv;
        }
    }
    float w4r[4];
    {
        const bool up = (lane & 4) != 0;
        #pragma unroll
        for (int i = 0; i < 4; i++) {
            float send = up ? w8[i] : w8[i + 4];
            float recv = __shfl_xor_sync(0xFFFFFFFFu, send, 4);
            w4r[i] = (up ? w8[i + 4] : w8[i]) + recv;
        }
    }
    float w2[2];
    {
        const bool up = (lane & 2) != 0;
        #pragma unroll
        for (int i = 0; i < 2; i++) {
            float snd = up ? w4r[i] : w4r[i + 2];
            float rcv = __shfl_xor_sync(0xFFFFFFFFu, snd, 2);
            w2[i] = (up ? w4r[i + 2] : w4r[i]) + rcv;
        }
    }
    float w1;
    {
        const bool up = (lane & 1) != 0;
        float snd = up ? w2[0] : w2[1];
        float rcv = __shfl_xor_sync(0xFFFFFFFFu, snd, 1);
        w1 = (up ? w2[1] : w2[0]) + rcv;
    }
    if (lane < KNN)
        out[(long long)n * KNN + lane] = w1 + bout;

    const float inv = 1.f / (float)KNN;
    float4 os = make_float4(acc.x * inv, acc.y * inv, acc.z * inv, acc.w * inv);
    *(float4*)(out + (long long)N_NODES * KNN + (long long)n * D + c4) = os;
}

// ---------------------------------------------------------------------------
extern "C" void kernel_launch(void* const* d_in, const int* in_sizes, int n_in,
                              void* d_out, int out_size)
{
    const float* feature = (const float*)d_in[0];   // [N,128]
    const float* dmax    = (const float*)d_in[1];   // [N,16]
    const void*  dargm   = (const void*)d_in[2];    // [N,16] i32/i64
    const float* W       = (const float*)d_in[3];   // [256,128]
    const float* bh      = (const float*)d_in[4];   // [128]
    const float* wo      = (const float*)d_in[5];   // [128,1]
    const float* bo      = (const float*)d_in[6];   // [1]
    float* out = (float*)d_out;

    size_t smem_bytes = (size_t)(2 * 64 * WP + 2 * 64 * AP) * sizeof(unsigned); // 104448 B
    cudaFuncSetAttribute(pgnn_gemm_kernel,
                         cudaFuncAttributeMaxDynamicSharedMemorySize,
                         (int)smem_bytes);
    dim3 grid((N_NODES + BROWS - 1) / BROWS, 2);   // 1563 x 2
    pgnn_gemm_kernel<<<grid, 256, smem_bytes>>>(feature, W,
                                                (const unsigned long long*)dargm);

    pgnn_gather_kernel<<<(N_NODES + 7) / 8, 256>>>(dmax, dargm, bh, wo, bo, out);
}